// round 16
// baseline (speedup 1.0000x reference)
#include <cuda_runtime.h>
#include <cuda_bf16.h>
#include <cstdint>

#define D 64
#define K 32
#define VOCAB_MAX 100000
#define GRID_BLKS 296
#define TILE_B 4608            // 32 rows * 144B (ASTRIDE)
#define ASTRIDE_B 144
#define SMEM_W_OFF  73728      // 8 warps * 2 bufs * 4608
#define SMEM_B1_OFF 92160
#define SMEM_B2_OFF 92416
#define SMEM_W3_OFF 92672
#define SMEM_TOTAL  92928

// Scratch (alloc-free rule): bf16 P/Q
__device__ unsigned short g_Pb[(size_t)VOCAB_MAX * D];   // bf16(u2e @ W1a)
__device__ unsigned short g_Qb[(size_t)VOCAB_MAX * D];   // bf16(u2e @ W1b + b1)
__device__ int g_flags[1];     // != 0 -> mask buffer is bytes (else 32-bit words)
__device__ int g_bar_count;    // global barrier: arrival counter (returns to 0 every launch)
__device__ int g_bar_flag;     // global barrier: phase flag (parity alternates per launch)

// ======================= helpers =======================
__device__ __forceinline__ uint32_t smem_to_u32(const void* p) {
    uint32_t a;
    asm("{ .reg .u64 t; cvta.to.shared.u64 t, %1; cvt.u32.u64 %0, t; }" : "=r"(a) : "l"(p));
    return a;
}
#define CVT_BF16X2_F32(result, a, b) \
    asm("cvt.rn.satfinite.bf16x2.f32 %0, %1, %2;" : "=r"(result) : "f"(b), "f"(a))
#define ADD_BF16X2(r, a, b) \
    asm("add.bf16x2 %0, %1, %2;" : "=r"(r) : "r"(a), "r"(b))
#define MAX_BF16X2(r, a, b) \
    asm("max.bf16x2 %0, %1, %2;" : "=r"(r) : "r"(a), "r"(b))

#define LDMATRIX_X4(r0, r1, r2, r3, addr) \
    asm volatile("ldmatrix.sync.aligned.m8n8.x4.shared.b16 {%0,%1,%2,%3}, [%4];" \
        : "=r"(r0), "=r"(r1), "=r"(r2), "=r"(r3) : "r"(addr))
#define LDMATRIX_X4_TRANS(r0, r1, r2, r3, addr) \
    asm volatile("ldmatrix.sync.aligned.m8n8.x4.trans.shared.b16 {%0,%1,%2,%3}, [%4];" \
        : "=r"(r0), "=r"(r1), "=r"(r2), "=r"(r3) : "r"(addr))

// D (f32) += A (bf16) x B (bf16); C==D accumulate in place
#define MMA16816(d0, d1, d2, d3, a0, a1, a2, a3, b0, b1) \
    asm volatile("mma.sync.aligned.m16n8k16.row.col.f32.bf16.bf16.f32 " \
        "{%0,%1,%2,%3}, {%4,%5,%6,%7}, {%8,%9}, {%0,%1,%2,%3};" \
        : "+f"(d0), "+f"(d1), "+f"(d2), "+f"(d3) \
        : "r"(a0), "r"(a1), "r"(a2), "r"(a3), "r"(b0), "r"(b1))

// ======================= fused kernel: prep -> global barrier -> agg =======================
__global__ __launch_bounds__(256, 2) void fused_kernel(
    const float* __restrict__ u2e,
    const float* __restrict__ W1, const float* __restrict__ b1,
    const float* __restrict__ W2, const float* __restrict__ b2,
    const float* __restrict__ W3,
    const int* __restrict__ nodes, const int* __restrict__ neigh_idx,
    const void* __restrict__ maskbuf, const unsigned int* __restrict__ mbuf,
    int n_words, float* __restrict__ out, int n_nodes, int V) {
    extern __shared__ __align__(16) unsigned char smem[];
    int tid = threadIdx.x, warp = tid >> 5, lane = tid & 31;
    unsigned char* sW = smem + SMEM_W_OFF;
    float* sb1 = (float*)(smem + SMEM_B1_OFF);
    float* sb2 = (float*)(smem + SMEM_B2_OFF);
    float* sW3 = (float*)(smem + SMEM_W3_OFF);
    uint32_t w_base = smem_to_u32(sW);

    // ---- mask dtype scan (byte vs word); 0->1 idempotent across graph replays ----
    {
        int byte_det = 0;
        for (int i = blockIdx.x * 256 + tid; i < n_words; i += gridDim.x * 256) {
            unsigned int w = mbuf[i];
            if (w != 0u && w != 1u && w != 0x3f800000u) { byte_det = 1; break; }
        }
        if (byte_det) atomicOr(&g_flags[0], 1);
    }

    // ================= PREP PHASE =================
    // Stage W1 [128 k][64 n] bf16 into sW (144B rows)
    for (int p = tid; p < 128 * 32; p += 256) {
        int r = p >> 5, cp = p & 31;
        uint32_t v;
        CVT_BF16X2_F32(v, W1[(size_t)r * 64 + 2 * cp], W1[(size_t)r * 64 + 2 * cp + 1]);
        *(uint32_t*)(sW + r * ASTRIDE_B + cp * 4) = v;
    }
    if (tid < 64) { sb1[tid] = b1[tid]; sb2[tid] = b2[tid]; sW3[tid] = W3[tid]; }
    __syncthreads();

    const int j0 = 2 * (lane & 3);
    const int r0 = lane >> 2;

    for (int rb = blockIdx.x; rb * 256 < V; rb += gridDim.x) {
        int blk_v0 = rb * 256;
        // cooperative A staging: 256 rows loaded as contiguous stream -> warp tiles (buf 0)
        for (int i = tid; i < 256 * 16; i += 256) {
            int row = i >> 4, segi = i & 15;
            int grow = blk_v0 + row;
            if (grow >= V) grow = V - 1;
            float4 f = *(const float4*)(u2e + (size_t)grow * D + segi * 4);
            uint2 w;
            CVT_BF16X2_F32(w.x, f.x, f.y);
            CVT_BF16X2_F32(w.y, f.z, f.w);
            *(uint2*)(smem + (row >> 5) * 2 * TILE_B + (row & 31) * ASTRIDE_B + segi * 8) = w;
        }
        __syncthreads();

        int v0 = blk_v0 + warp * 32;
        unsigned char* myTile = smem + warp * 2 * TILE_B;   // buf 0
        uint32_t a_base = smem_to_u32(myTile);
        uint32_t af[2][4][4];
#pragma unroll
        for (int mt = 0; mt < 2; mt++)
#pragma unroll
            for (int ks = 0; ks < 4; ks++) {
                uint32_t addr = a_base + (mt * 16 + (lane & 15)) * ASTRIDE_B + ks * 32 + (lane >> 4) * 16;
                LDMATRIX_X4(af[mt][ks][0], af[mt][ks][1], af[mt][ks][2], af[mt][ks][3], addr);
            }
        __syncwarp();

#pragma unroll
        for (int half = 0; half < 2; half++) {
            unsigned short* gOut = half ? g_Qb : g_Pb;
#pragma unroll
            for (int nt = 0; nt < 8; nt++) {
                uint32_t b[4][2];
                {
                    uint32_t r0b, r1b, r2b, r3b;
                    uint32_t addr = w_base + (half * 64 + lane) * ASTRIDE_B + nt * 16;
                    LDMATRIX_X4_TRANS(r0b, r1b, r2b, r3b, addr);
                    b[0][0] = r0b; b[0][1] = r1b; b[1][0] = r2b; b[1][1] = r3b;
                    addr = w_base + (half * 64 + 32 + lane) * ASTRIDE_B + nt * 16;
                    LDMATRIX_X4_TRANS(r0b, r1b, r2b, r3b, addr);
                    b[2][0] = r0b; b[2][1] = r1b; b[3][0] = r2b; b[3][1] = r3b;
                }
                int j = nt * 8 + j0;
                float init0 = half ? sb1[j] : 0.f;
                float init1 = half ? sb1[j + 1] : 0.f;
#pragma unroll
                for (int mt = 0; mt < 2; mt++) {
                    float d0 = init0, d1 = init1, d2 = init0, d3 = init1;
#pragma unroll
                    for (int ks = 0; ks < 4; ks++)
                        MMA16816(d0, d1, d2, d3,
                                 af[mt][ks][0], af[mt][ks][1], af[mt][ks][2], af[mt][ks][3],
                                 b[ks][0], b[ks][1]);
                    uint32_t wlo, whi;
                    CVT_BF16X2_F32(wlo, d0, d1);
                    CVT_BF16X2_F32(whi, d2, d3);
                    *(uint32_t*)(myTile + (mt * 16 + r0) * ASTRIDE_B + nt * 16 + (lane & 3) * 4) = wlo;
                    *(uint32_t*)(myTile + (mt * 16 + r0 + 8) * ASTRIDE_B + nt * 16 + (lane & 3) * 4) = whi;
                }
            }
            __syncwarp();
            for (int i = lane; i < 256; i += 32) {
                int row = i >> 3, segi = i & 7;
                uint4 v = *(uint4*)(myTile + row * ASTRIDE_B + segi * 16);
                int grow = v0 + row;
                if (grow < V)
                    *(uint4*)(gOut + (size_t)grow * D + segi * 8) = v;
            }
            __syncwarp();
        }
        __syncthreads();   // tiles reused by next rb's staging
    }

    // ================= GLOBAL BARRIER (sense-reversing; all 296 blocks co-resident) =====
    __syncthreads();
    if (tid == 0) {
        __threadfence();                               // release P/Q writes
        int phase = atomicAdd(&g_bar_flag, 0);         // read phase BEFORE arriving
        int prev = atomicAdd(&g_bar_count, 1);
        if (prev == (int)gridDim.x - 1) {
            g_bar_count = 0;
            __threadfence();
            atomicExch(&g_bar_flag, phase ^ 1);
        } else {
            while (atomicAdd(&g_bar_flag, 0) == phase) { }
        }
        __threadfence();                               // acquire
    }
    __syncthreads();

    // ================= AGG PHASE =================
    // Stage W2 [64 k][64 n] bf16 over the W1 region
    for (int p = tid; p < 64 * 32; p += 256) {
        int r = p >> 5, cp = p & 31;
        uint32_t v;
        CVT_BF16X2_F32(v, W2[(size_t)r * 64 + 2 * cp], W2[(size_t)r * 64 + 2 * cp + 1]);
        *(uint32_t*)(sW + r * ASTRIDE_B + cp * 4) = v;
    }
    __syncthreads();

    // half B-fragment hoist (nt 0..3)
    uint32_t bfh[4][4][2];
#pragma unroll
    for (int nt = 0; nt < 4; nt++) {
        uint32_t r0b, r1b, r2b, r3b;
        uint32_t addr = w_base + lane * ASTRIDE_B + nt * 16;
        LDMATRIX_X4_TRANS(r0b, r1b, r2b, r3b, addr);
        bfh[nt][0][0] = r0b; bfh[nt][0][1] = r1b; bfh[nt][1][0] = r2b; bfh[nt][1][1] = r3b;
        addr = w_base + (32 + lane) * ASTRIDE_B + nt * 16;
        LDMATRIX_X4_TRANS(r0b, r1b, r2b, r3b, addr);
        bfh[nt][2][0] = r0b; bfh[nt][2][1] = r1b; bfh[nt][3][0] = r2b; bfh[nt][3][1] = r3b;
    }

    const int byte_mode = g_flags[0];
    const int j0l = j0;
    const int seg = lane & 7;
    const int rsub = lane >> 3;
    const int erow_sub = lane >> 4;
    const int ecol = (lane & 15) * 4;
    const int rbase = lane >> 2;
    int wg = blockIdx.x * 8 + warp;
    int stride = gridDim.x * 8;

    if (wg < n_nodes) {
        // ---- prologue: build node wg's A tile in buf 0 ----
        int idx, m;
        {
            int node = nodes[wg];
            idx = neigh_idx[(size_t)wg * K + lane];
            if (byte_mode)
                m = ((const unsigned char*)maskbuf)[(size_t)wg * K + lane] != 0;
            else
                m = ((const unsigned int*)maskbuf)[(size_t)wg * K + lane] != 0u;
            uint4 q4 = *(const uint4*)(g_Qb + (size_t)node * D + seg * 8);
            unsigned char* t0 = smem + warp * 2 * TILE_B;
#pragma unroll
            for (int it = 0; it < 8; it++) {
                int ridx = __shfl_sync(0xffffffffu, idx, it * 4 + rsub);
                uint4 p = *(const uint4*)(g_Pb + (size_t)ridx * D + seg * 8);
                uint4 w;
                ADD_BF16X2(w.x, p.x, q4.x); MAX_BF16X2(w.x, w.x, 0u);
                ADD_BF16X2(w.y, p.y, q4.y); MAX_BF16X2(w.y, w.y, 0u);
                ADD_BF16X2(w.z, p.z, q4.z); MAX_BF16X2(w.z, w.z, 0u);
                ADD_BF16X2(w.w, p.w, q4.w); MAX_BF16X2(w.w, w.w, 0u);
                *(uint4*)(t0 + (it * 4 + rsub) * ASTRIDE_B + seg * 16) = w;
            }
        }
        __syncwarp();
        int cur = 0;

        for (int n = wg; n < n_nodes; n += stride) {
            // ---- A fragments from current tile (stored last iteration's tail) ----
            uint32_t a_base = smem_to_u32(smem + (warp * 2 + cur) * TILE_B);
            uint32_t af[2][4][4];
#pragma unroll
            for (int mt = 0; mt < 2; mt++)
#pragma unroll
                for (int ks = 0; ks < 4; ks++) {
                    uint32_t addr = a_base + (mt * 16 + (lane & 15)) * ASTRIDE_B + ks * 32 + (lane >> 4) * 16;
                    LDMATRIX_X4(af[mt][ks][0], af[mt][ks][1], af[mt][ks][2], af[mt][ks][3], addr);
                }

            // ---- prefetch next node's front-end (loads overlap MMA/softmax/epilogue) ----
            int n2 = n + stride;
            int nc2 = (n2 < n_nodes) ? n2 : n;
            int idx2 = neigh_idx[(size_t)nc2 * K + lane];
            int m2;
            if (byte_mode)
                m2 = ((const unsigned char*)maskbuf)[(size_t)nc2 * K + lane] != 0;
            else
                m2 = ((const unsigned int*)maskbuf)[(size_t)nc2 * K + lane] != 0u;
            int node2 = nodes[nc2];
            uint4 q42 = *(const uint4*)(g_Qb + (size_t)node2 * D + seg * 8);
            uint4 p42[8];
#pragma unroll
            for (int it = 0; it < 8; it++) {
                int ridx = __shfl_sync(0xffffffffu, idx2, it * 4 + rsub);
                p42[it] = *(const uint4*)(g_Pb + (size_t)ridx * D + seg * 8);
            }

            // ---- layer 2 (HMMA) + layer 3 folded per n-tile ----
            float sp0 = 0.f, sp1 = 0.f, sp2 = 0.f, sp3 = 0.f;
#pragma unroll
            for (int nt = 0; nt < 8; nt++) {
                uint32_t b[4][2];
                if (nt < 4) {
#pragma unroll
                    for (int ks = 0; ks < 4; ks++) { b[ks][0] = bfh[nt][ks][0]; b[ks][1] = bfh[nt][ks][1]; }
                } else {
                    uint32_t r0b, r1b, r2b, r3b;
                    uint32_t addr = w_base + lane * ASTRIDE_B + nt * 16;
                    LDMATRIX_X4_TRANS(r0b, r1b, r2b, r3b, addr);
                    b[0][0] = r0b; b[0][1] = r1b; b[1][0] = r2b; b[1][1] = r3b;
                    addr = w_base + (32 + lane) * ASTRIDE_B + nt * 16;
                    LDMATRIX_X4_TRANS(r0b, r1b, r2b, r3b, addr);
                    b[2][0] = r0b; b[2][1] = r1b; b[3][0] = r2b; b[3][1] = r3b;
                }
                int j = nt * 8 + j0l;
                float bb0 = sb2[j], bb1 = sb2[j + 1];
                float w30 = sW3[j], w31 = sW3[j + 1];
#pragma unroll
                for (int mt = 0; mt < 2; mt++) {
                    float d0 = bb0, d1 = bb1, d2 = bb0, d3 = bb1;
#pragma unroll
                    for (int ks = 0; ks < 4; ks++)
                        MMA16816(d0, d1, d2, d3,
                                 af[mt][ks][0], af[mt][ks][1], af[mt][ks][2], af[mt][ks][3],
                                 b[ks][0], b[ks][1]);
                    float lo = fmaf(fmaxf(d0, 0.f), w30, fmaf(fmaxf(d1, 0.f), w31, 0.f));
                    float hi = fmaf(fmaxf(d2, 0.f), w30, fmaf(fmaxf(d3, 0.f), w31, 0.f));
                    if (mt == 0) { sp0 += lo; sp1 += hi; } else { sp2 += lo; sp3 += hi; }
                }
            }

            // ---- early-issue first half of epilogue E gather ----
            float4 ev[8];
#pragma unroll
            for (int it = 0; it < 8; it++) {
                int row = it * 2 + erow_sub;
                int ridx = __shfl_sync(0xffffffffu, idx, row);
                ev[it] = *(const float4*)(u2e + (size_t)ridx * D + ecol);
            }

            // ---- per-row score completion ----
            sp0 += __shfl_xor_sync(0xffffffffu, sp0, 1); sp0 += __shfl_xor_sync(0xffffffffu, sp0, 2);
            sp1 += __shfl_xor_sync(0xffffffffu, sp1, 1); sp1 += __shfl_xor_sync(0xffffffffu, sp1, 2);
            sp2 += __shfl_xor_sync(0xffffffffu, sp2, 1); sp2 += __shfl_xor_sync(0xffffffffu, sp2, 2);
            sp3 += __shfl_xor_sync(0xffffffffu, sp3, 1); sp3 += __shfl_xor_sync(0xffffffffu, sp3, 2);

            // ---- distributed masked softmax (b3 softmax-invariant) ----
            unsigned int mask32 = __ballot_sync(0xffffffffu, m);
            float s0 = ((mask32 >> rbase) & 1u)        ? sp0 : -1e30f;
            float s1 = ((mask32 >> (rbase + 8)) & 1u)  ? sp1 : -1e30f;
            float s2 = ((mask32 >> (rbase + 16)) & 1u) ? sp2 : -1e30f;
            float s3 = ((mask32 >> (rbase + 24)) & 1u) ? sp3 : -1e30f;
            float mx = fmaxf(fmaxf(s0, s1), fmaxf(s2, s3));
            mx = fmaxf(mx, __shfl_xor_sync(0xffffffffu, mx, 4));
            mx = fmaxf(mx, __shfl_xor_sync(0xffffffffu, mx, 8));
            mx = fmaxf(mx, __shfl_xor_sync(0xffffffffu, mx, 16));
            float e0 = __expf(s0 - mx), e1 = __expf(s1 - mx);
            float e2 = __expf(s2 - mx), e3 = __expf(s3 - mx);
            float ssum = (e0 + e1) + (e2 + e3);
            ssum += __shfl_xor_sync(0xffffffffu, ssum, 4);
            ssum += __shfl_xor_sync(0xffffffffu, ssum, 8);
            ssum += __shfl_xor_sync(0xffffffffu, ssum, 16);
            float inv = __fdividef(1.f, ssum);
            float att0 = e0 * inv, att1 = e1 * inv, att2 = e2 * inv, att3 = e3 * inv;

            // ---- epilogue ----
            float a0 = 0.f, a1 = 0.f, a2 = 0.f, a3 = 0.f;
#pragma unroll
            for (int it = 0; it < 8; it++) {
                const int oct = it >> 2;
                float att_oct = (oct == 0) ? att0 : att1;
                int row = it * 2 + erow_sub;
                float attr = __shfl_sync(0xffffffffu, att_oct, (row & 7) * 4);
                a0 = fmaf(attr, ev[it].x, a0);
                a1 = fmaf(attr, ev[it].y, a1);
                a2 = fmaf(attr, ev[it].z, a2);
                a3 = fmaf(attr, ev[it].w, a3);
            }
#pragma unroll
            for (int it = 8; it < 16; it++) {
                const int oct = it >> 2;
                float att_oct = (oct == 2) ? att2 : att3;
                int row = it * 2 + erow_sub;
                float attr = __shfl_sync(0xffffffffu, att_oct, (row & 7) * 4);
                int ridx = __shfl_sync(0xffffffffu, idx, row);
                float4 v = *(const float4*)(u2e + (size_t)ridx * D + ecol);
                a0 = fmaf(attr, v.x, a0);
                a1 = fmaf(attr, v.y, a1);
                a2 = fmaf(attr, v.z, a2);
                a3 = fmaf(attr, v.w, a3);
            }
            a0 += __shfl_xor_sync(0xffffffffu, a0, 16);
            a1 += __shfl_xor_sync(0xffffffffu, a1, 16);
            a2 += __shfl_xor_sync(0xffffffffu, a2, 16);
            a3 += __shfl_xor_sync(0xffffffffu, a3, 16);
            if (lane < 16)
                *(float4*)(out + (size_t)n * D + ecol) = make_float4(a0, a1, a2, a3);

            // ---- tail: build NEXT node's A tile in the alternate buffer ----
            {
                unsigned char* tN = smem + (warp * 2 + (cur ^ 1)) * TILE_B;
#pragma unroll
                for (int it = 0; it < 8; it++) {
                    uint4 w;
                    ADD_BF16X2(w.x, p42[it].x, q42.x); MAX_BF16X2(w.x, w.x, 0u);
                    ADD_BF16X2(w.y, p42[it].y, q42.y); MAX_BF16X2(w.y, w.y, 0u);
                    ADD_BF16X2(w.z, p42[it].z, q42.z); MAX_BF16X2(w.z, w.z, 0u);
                    ADD_BF16X2(w.w, p42[it].w, q42.w); MAX_BF16X2(w.w, w.w, 0u);
                    *(uint4*)(tN + (it * 4 + rsub) * ASTRIDE_B + seg * 16) = w;
                }
            }
            __syncwarp();
            idx = idx2; m = m2; cur ^= 1;
        }
    }
}

// ======================= launch =======================
// Input order (metadata): u2e, W1, b1, W2, b2, W3, b3, nodes, neigh_idx, neigh_mask
extern "C" void kernel_launch(void* const* d_in, const int* in_sizes, int n_in,
                              void* d_out, int out_size) {
    const float* u2e = (const float*)d_in[0];
    const float* W1  = (const float*)d_in[1];
    const float* b1  = (const float*)d_in[2];
    const float* W2  = (const float*)d_in[3];
    const float* b2  = (const float*)d_in[4];
    const float* W3  = (const float*)d_in[5];
    const int*   nodes     = (const int*)d_in[7];
    const int*   neigh_idx = (const int*)d_in[8];
    const void*  neigh_mask = d_in[9];
    float* out = (float*)d_out;

    int V = in_sizes[0] / D;
    if (V > VOCAB_MAX) V = VOCAB_MAX;
    int n_nodes = in_sizes[7];
    int n_words = in_sizes[9] / 4;   // safe lower bound under both dtypes

    cudaFuncSetAttribute(fused_kernel, cudaFuncAttributeMaxDynamicSharedMemorySize, SMEM_TOTAL);
    fused_kernel<<<GRID_BLKS, 256, SMEM_TOTAL>>>(
        u2e, W1, b1, W2, b2, W3,
        nodes, neigh_idx, neigh_mask, (const unsigned int*)neigh_mask,
        n_words, out, n_nodes, V);
}

// round 17
// speedup vs baseline: 1.0479x; 1.0479x over previous
#include <cuda_runtime.h>
#include <cuda_bf16.h>
#include <cstdint>

#define D 64
#define K 32
#define VOCAB_MAX 100000
#define ASTRIDE_B 144
#define TILE_B 4608                       // 32 rows * 144B
#define AGG_W2_OFF   73728                // 8 warps * 2 bufs * TILE_B
#define AGG_B2_OFF   82944
#define AGG_W3_OFF   83200
#define AGG_SMEM_TOT 83456

// Scratch (alloc-free rule): bf16 P/Q
__device__ unsigned short g_Pb[(size_t)VOCAB_MAX * D];   // bf16(u2e @ W1a)
__device__ unsigned short g_Qb[(size_t)VOCAB_MAX * D];   // bf16(u2e @ W1b + b1)
__device__ int g_flags[1];   // [0] != 0 -> mask buffer is bytes (else 32-bit words)

// ======================= helpers =======================
__device__ __forceinline__ uint32_t smem_to_u32(const void* p) {
    uint32_t a;
    asm("{ .reg .u64 t; cvta.to.shared.u64 t, %1; cvt.u32.u64 %0, t; }" : "=r"(a) : "l"(p));
    return a;
}
#define CVT_BF16X2_F32(result, a, b) \
    asm("cvt.rn.satfinite.bf16x2.f32 %0, %1, %2;" : "=r"(result) : "f"(b), "f"(a))
#define ADD_BF16X2(r, a, b) \
    asm("add.bf16x2 %0, %1, %2;" : "=r"(r) : "r"(a), "r"(b))
#define MAX_BF16X2(r, a, b) \
    asm("max.bf16x2 %0, %1, %2;" : "=r"(r) : "r"(a), "r"(b))

#define LDMATRIX_X4(r0, r1, r2, r3, addr) \
    asm volatile("ldmatrix.sync.aligned.m8n8.x4.shared.b16 {%0,%1,%2,%3}, [%4];" \
        : "=r"(r0), "=r"(r1), "=r"(r2), "=r"(r3) : "r"(addr))
#define LDMATRIX_X4_TRANS(r0, r1, r2, r3, addr) \
    asm volatile("ldmatrix.sync.aligned.m8n8.x4.trans.shared.b16 {%0,%1,%2,%3}, [%4];" \
        : "=r"(r0), "=r"(r1), "=r"(r2), "=r"(r3) : "r"(addr))

// D (f32) += A (bf16) x B (bf16); C==D accumulate in place
#define MMA16816(d0, d1, d2, d3, a0, a1, a2, a3, b0, b1) \
    asm volatile("mma.sync.aligned.m16n8k16.row.col.f32.bf16.bf16.f32 " \
        "{%0,%1,%2,%3}, {%4,%5,%6,%7}, {%8,%9}, {%0,%1,%2,%3};" \
        : "+f"(d0), "+f"(d1), "+f"(d2), "+f"(d3) \
        : "r"(a0), "r"(a1), "r"(a2), "r"(a3), "r"(b0), "r"(b1))

// ======================= prep: P/Q (bf16 out) + mask dtype scan =======================
// Cooperative I/O (R15): block-contiguous loads + SMEM-staged contiguous stores.
__global__ __launch_bounds__(128) void prep_mma_kernel(const float* __restrict__ u2e,
                                                       const float* __restrict__ W1,
                                                       const float* __restrict__ b1,
                                                       int V,
                                                       const unsigned int* __restrict__ mbuf,
                                                       int n_words) {
    __shared__ __align__(16) unsigned char sA[4][32 * ASTRIDE_B];
    __shared__ __align__(16) unsigned char sW[128 * ASTRIDE_B];  // W1 [128 k][64 n] bf16
    __shared__ float sb1[64];
    int tid = threadIdx.x, warp = tid >> 5, lane = tid & 31;

    // ---- mask dtype scan (byte vs word); 0->1 idempotent across graph replays ----
    {
        int byte_mode = 0;
        for (int i = blockIdx.x * blockDim.x + tid; i < n_words; i += gridDim.x * blockDim.x) {
            unsigned int w = mbuf[i];
            if (w != 0u && w != 1u && w != 0x3f800000u) { byte_mode = 1; break; }
        }
        if (byte_mode) atomicOr(&g_flags[0], 1);
    }

    // ---- stage W1 (bf16, padded rows) ----
    for (int p = tid; p < 128 * 32; p += 128) {
        int r = p >> 5, cp = p & 31;
        uint32_t v;
        CVT_BF16X2_F32(v, W1[(size_t)r * 64 + 2 * cp], W1[(size_t)r * 64 + 2 * cp + 1]);
        *(uint32_t*)(sW + r * ASTRIDE_B + cp * 4) = v;
    }
    if (tid < 64) sb1[tid] = b1[tid];

    // ---- cooperative A staging: block's 128 rows as one contiguous stream ----
    int blk_v0 = blockIdx.x * 128;
    for (int i = tid; i < 128 * 16; i += 128) {
        int row = i >> 4;
        int seg = i & 15;
        int grow = blk_v0 + row;
        if (grow >= V) grow = V - 1;
        float4 f = *(const float4*)(u2e + (size_t)grow * D + seg * 4);
        uint2 w;
        CVT_BF16X2_F32(w.x, f.x, f.y);
        CVT_BF16X2_F32(w.y, f.z, f.w);
        *(uint2*)(sA[row >> 5] + (row & 31) * ASTRIDE_B + seg * 8) = w;
    }
    __syncthreads();

    int v0 = blk_v0 + warp * 32;

    uint32_t af[2][4][4];
    uint32_t a_base = smem_to_u32(sA[warp]);
#pragma unroll
    for (int mt = 0; mt < 2; mt++)
#pragma unroll
        for (int ks = 0; ks < 4; ks++) {
            uint32_t addr = a_base + (mt * 16 + (lane & 15)) * ASTRIDE_B + ks * 32 + (lane >> 4) * 16;
            LDMATRIX_X4(af[mt][ks][0], af[mt][ks][1], af[mt][ks][2], af[mt][ks][3], addr);
        }
    __syncwarp();

    uint32_t w_base = smem_to_u32(sW);
    int j0 = 2 * (lane & 3);
    int r0 = lane >> 2;

#pragma unroll
    for (int half = 0; half < 2; half++) {
        unsigned short* gOut = half ? g_Qb : g_Pb;
#pragma unroll
        for (int nt = 0; nt < 8; nt++) {
            uint32_t b[4][2];
            {
                uint32_t r0b, r1b, r2b, r3b;
                uint32_t addr = w_base + (half * 64 + lane) * ASTRIDE_B + nt * 16;
                LDMATRIX_X4_TRANS(r0b, r1b, r2b, r3b, addr);
                b[0][0] = r0b; b[0][1] = r1b; b[1][0] = r2b; b[1][1] = r3b;
                addr = w_base + (half * 64 + 32 + lane) * ASTRIDE_B + nt * 16;
                LDMATRIX_X4_TRANS(r0b, r1b, r2b, r3b, addr);
                b[2][0] = r0b; b[2][1] = r1b; b[3][0] = r2b; b[3][1] = r3b;
            }
            int j = nt * 8 + j0;
            float init0 = half ? sb1[j] : 0.f;
            float init1 = half ? sb1[j + 1] : 0.f;
#pragma unroll
            for (int mt = 0; mt < 2; mt++) {
                float d0 = init0, d1 = init1, d2 = init0, d3 = init1;
#pragma unroll
                for (int ks = 0; ks < 4; ks++)
                    MMA16816(d0, d1, d2, d3,
                             af[mt][ks][0], af[mt][ks][1], af[mt][ks][2], af[mt][ks][3],
                             b[ks][0], b[ks][1]);
                uint32_t wlo, whi;
                CVT_BF16X2_F32(wlo, d0, d1);
                CVT_BF16X2_F32(whi, d2, d3);
                *(uint32_t*)(sA[warp] + (mt * 16 + r0) * ASTRIDE_B + nt * 16 + (lane & 3) * 4) = wlo;
                *(uint32_t*)(sA[warp] + (mt * 16 + r0 + 8) * ASTRIDE_B + nt * 16 + (lane & 3) * 4) = whi;
            }
        }
        __syncwarp();
        for (int i = lane; i < 256; i += 32) {
            int row = i >> 3;
            int seg = i & 7;
            uint4 v = *(uint4*)(sA[warp] + row * ASTRIDE_B + seg * 16);
            int grow = v0 + row;
            if (grow < V)
                *(uint4*)(gOut + (size_t)grow * D + seg * 8) = v;
        }
        __syncwarp();
    }
}

// ======================= agg: persistent; double-buffered A tiles (tail store) ==========
// R15 agg with one change: next node's layer-1 output is written into the ALTERNATE
// per-warp tile at iteration end (its P loads had the whole body to land), so the
// loop top opens directly with ldmatrix — no STS on the critical path.
__global__ __launch_bounds__(256, 2) void agg_mma_kernel(
    const float* __restrict__ u2e,
    const float* __restrict__ W2, const float* __restrict__ b2,
    const float* __restrict__ W3,
    const int* __restrict__ nodes, const int* __restrict__ neigh_idx,
    const void* __restrict__ maskbuf,
    float* __restrict__ out, int n_nodes) {
    extern __shared__ __align__(16) unsigned char smem[];
    unsigned char* sW2 = smem + AGG_W2_OFF;
    float* sb2 = (float*)(smem + AGG_B2_OFF);
    float* sW3 = (float*)(smem + AGG_W3_OFF);
    int tid = threadIdx.x, warp = tid >> 5, lane = tid & 31;

    for (int p = tid; p < 64 * 32; p += 256) {
        int r = p >> 5, cp = p & 31;
        uint32_t v;
        CVT_BF16X2_F32(v, W2[(size_t)r * 64 + 2 * cp], W2[(size_t)r * 64 + 2 * cp + 1]);
        *(uint32_t*)(sW2 + r * ASTRIDE_B + cp * 4) = v;
    }
    if (tid < 64) { sb2[tid] = b2[tid]; sW3[tid] = W3[tid]; }
    __syncthreads();

    uint32_t w_base = smem_to_u32(sW2);

    // ---- hoist B fragments for n-tiles 0..3 only (register budget) ----
    uint32_t bfh[4][4][2];
#pragma unroll
    for (int nt = 0; nt < 4; nt++) {
        uint32_t r0b, r1b, r2b, r3b;
        uint32_t addr = w_base + lane * ASTRIDE_B + nt * 16;
        LDMATRIX_X4_TRANS(r0b, r1b, r2b, r3b, addr);
        bfh[nt][0][0] = r0b; bfh[nt][0][1] = r1b; bfh[nt][1][0] = r2b; bfh[nt][1][1] = r3b;
        addr = w_base + (32 + lane) * ASTRIDE_B + nt * 16;
        LDMATRIX_X4_TRANS(r0b, r1b, r2b, r3b, addr);
        bfh[nt][2][0] = r0b; bfh[nt][2][1] = r1b; bfh[nt][3][0] = r2b; bfh[nt][3][1] = r3b;
    }

    const int byte_mode = g_flags[0];
    const int j0l = 2 * (lane & 3);
    const int seg = lane & 7;        // 16B segment within a 128B bf16 row
    const int rsub = lane >> 3;      // 0..3 (row within a 4-row load group)
    const int erow_sub = lane >> 4;  // 0..1 (row parity for epilogue)
    const int ecol = (lane & 15) * 4;
    const int rbase = lane >> 2;     // base row this lane's scores belong to
    int wg = blockIdx.x * 8 + warp;
    int stride = gridDim.x * 8;

    if (wg >= n_nodes) return;

    // ---- prologue: build node wg's A tile in buf 0 ----
    int idx, m;
    {
        int node = nodes[wg];
        idx = neigh_idx[(size_t)wg * K + lane];
        if (byte_mode)
            m = ((const unsigned char*)maskbuf)[(size_t)wg * K + lane] != 0;
        else
            m = ((const unsigned int*)maskbuf)[(size_t)wg * K + lane] != 0u;
        uint4 q4 = *(const uint4*)(g_Qb + (size_t)node * D + seg * 8);
        unsigned char* t0 = smem + warp * 2 * TILE_B;
#pragma unroll
        for (int it = 0; it < 8; it++) {
            int ridx = __shfl_sync(0xffffffffu, idx, it * 4 + rsub);
            uint4 p = *(const uint4*)(g_Pb + (size_t)ridx * D + seg * 8);
            uint4 w;
            ADD_BF16X2(w.x, p.x, q4.x); MAX_BF16X2(w.x, w.x, 0u);
            ADD_BF16X2(w.y, p.y, q4.y); MAX_BF16X2(w.y, w.y, 0u);
            ADD_BF16X2(w.z, p.z, q4.z); MAX_BF16X2(w.z, w.z, 0u);
            ADD_BF16X2(w.w, p.w, q4.w); MAX_BF16X2(w.w, w.w, 0u);
            *(uint4*)(t0 + (it * 4 + rsub) * ASTRIDE_B + seg * 16) = w;
        }
    }
    __syncwarp();
    int cur = 0;

    for (int n = wg; n < n_nodes; n += stride) {
        // ---- A fragments straight from the current tile (built last iteration) ----
        uint32_t a_base = smem_to_u32(smem + (warp * 2 + cur) * TILE_B);
        uint32_t af[2][4][4];
#pragma unroll
        for (int mt = 0; mt < 2; mt++)
#pragma unroll
            for (int ks = 0; ks < 4; ks++) {
                uint32_t addr = a_base + (mt * 16 + (lane & 15)) * ASTRIDE_B + ks * 32 + (lane >> 4) * 16;
                LDMATRIX_X4(af[mt][ks][0], af[mt][ks][1], af[mt][ks][2], af[mt][ks][3], addr);
            }

        // ---- prefetch next node's front-end (loads overlap entire body) ----
        int n2 = n + stride;
        int nc2 = (n2 < n_nodes) ? n2 : n;
        int idx2 = neigh_idx[(size_t)nc2 * K + lane];
        int m2;
        if (byte_mode)
            m2 = ((const unsigned char*)maskbuf)[(size_t)nc2 * K + lane] != 0;
        else
            m2 = ((const unsigned int*)maskbuf)[(size_t)nc2 * K + lane] != 0u;
        int node2 = nodes[nc2];
        uint4 q42 = *(const uint4*)(g_Qb + (size_t)node2 * D + seg * 8);
        uint4 p42[8];
#pragma unroll
        for (int it = 0; it < 8; it++) {
            int ridx = __shfl_sync(0xffffffffu, idx2, it * 4 + rsub);
            p42[it] = *(const uint4*)(g_Pb + (size_t)ridx * D + seg * 8);
        }

        // ---- layer 2 (HMMA) + layer 3 folded per n-tile ----
        float sp0 = 0.f, sp1 = 0.f, sp2 = 0.f, sp3 = 0.f;
#pragma unroll
        for (int nt = 0; nt < 8; nt++) {
            uint32_t b[4][2];
            if (nt < 4) {
#pragma unroll
                for (int ks = 0; ks < 4; ks++) { b[ks][0] = bfh[nt][ks][0]; b[ks][1] = bfh[nt][ks][1]; }
            } else {
                uint32_t r0b, r1b, r2b, r3b;
                uint32_t addr = w_base + lane * ASTRIDE_B + nt * 16;
                LDMATRIX_X4_TRANS(r0b, r1b, r2b, r3b, addr);
                b[0][0] = r0b; b[0][1] = r1b; b[1][0] = r2b; b[1][1] = r3b;
                addr = w_base + (32 + lane) * ASTRIDE_B + nt * 16;
                LDMATRIX_X4_TRANS(r0b, r1b, r2b, r3b, addr);
                b[2][0] = r0b; b[2][1] = r1b; b[3][0] = r2b; b[3][1] = r3b;
            }
            int j = nt * 8 + j0l;
            float bb0 = sb2[j], bb1 = sb2[j + 1];
            float w30 = sW3[j], w31 = sW3[j + 1];
#pragma unroll
            for (int mt = 0; mt < 2; mt++) {
                float d0 = bb0, d1 = bb1, d2 = bb0, d3 = bb1;
#pragma unroll
                for (int ks = 0; ks < 4; ks++)
                    MMA16816(d0, d1, d2, d3,
                             af[mt][ks][0], af[mt][ks][1], af[mt][ks][2], af[mt][ks][3],
                             b[ks][0], b[ks][1]);
                float lo = fmaf(fmaxf(d0, 0.f), w30, fmaf(fmaxf(d1, 0.f), w31, 0.f));
                float hi = fmaf(fmaxf(d2, 0.f), w30, fmaf(fmaxf(d3, 0.f), w31, 0.f));
                if (mt == 0) { sp0 += lo; sp1 += hi; } else { sp2 += lo; sp3 += hi; }
            }
        }

        // ---- early-issue first half of epilogue E gather (depends only on idx) ----
        float4 ev[8];
#pragma unroll
        for (int it = 0; it < 8; it++) {
            int row = it * 2 + erow_sub;
            int ridx = __shfl_sync(0xffffffffu, idx, row);
            ev[it] = *(const float4*)(u2e + (size_t)ridx * D + ecol);
        }

        // ---- finish per-row scores ----
        sp0 += __shfl_xor_sync(0xffffffffu, sp0, 1); sp0 += __shfl_xor_sync(0xffffffffu, sp0, 2);
        sp1 += __shfl_xor_sync(0xffffffffu, sp1, 1); sp1 += __shfl_xor_sync(0xffffffffu, sp1, 2);
        sp2 += __shfl_xor_sync(0xffffffffu, sp2, 1); sp2 += __shfl_xor_sync(0xffffffffu, sp2, 2);
        sp3 += __shfl_xor_sync(0xffffffffu, sp3, 1); sp3 += __shfl_xor_sync(0xffffffffu, sp3, 2);

        // ---- distributed masked softmax (b3 softmax-invariant) ----
        unsigned int mask32 = __ballot_sync(0xffffffffu, m);
        float s0 = ((mask32 >> rbase) & 1u)        ? sp0 : -1e30f;
        float s1 = ((mask32 >> (rbase + 8)) & 1u)  ? sp1 : -1e30f;
        float s2 = ((mask32 >> (rbase + 16)) & 1u) ? sp2 : -1e30f;
        float s3 = ((mask32 >> (rbase + 24)) & 1u) ? sp3 : -1e30f;
        float mx = fmaxf(fmaxf(s0, s1), fmaxf(s2, s3));
        mx = fmaxf(mx, __shfl_xor_sync(0xffffffffu, mx, 4));
        mx = fmaxf(mx, __shfl_xor_sync(0xffffffffu, mx, 8));
        mx = fmaxf(mx, __shfl_xor_sync(0xffffffffu, mx, 16));
        float e0 = __expf(s0 - mx), e1 = __expf(s1 - mx);
        float e2 = __expf(s2 - mx), e3 = __expf(s3 - mx);
        float ssum = (e0 + e1) + (e2 + e3);
        ssum += __shfl_xor_sync(0xffffffffu, ssum, 4);
        ssum += __shfl_xor_sync(0xffffffffu, ssum, 8);
        ssum += __shfl_xor_sync(0xffffffffu, ssum, 16);
        float inv = __fdividef(1.f, ssum);
        float att0 = e0 * inv, att1 = e1 * inv, att2 = e2 * inv, att3 = e3 * inv;

        // ---- epilogue: consume prefetched rows 0..15, then gather rows 16..31 ----
        float a0 = 0.f, a1 = 0.f, a2 = 0.f, a3 = 0.f;
#pragma unroll
        for (int it = 0; it < 8; it++) {
            const int oct = it >> 2;
            float att_oct = (oct == 0) ? att0 : att1;
            int row = it * 2 + erow_sub;
            float attr = __shfl_sync(0xffffffffu, att_oct, (row & 7) * 4);
            a0 = fmaf(attr, ev[it].x, a0);
            a1 = fmaf(attr, ev[it].y, a1);
            a2 = fmaf(attr, ev[it].z, a2);
            a3 = fmaf(attr, ev[it].w, a3);
        }
#pragma unroll
        for (int it = 8; it < 16; it++) {
            const int oct = it >> 2;
            float att_oct = (oct == 2) ? att2 : att3;
            int row = it * 2 + erow_sub;
            float attr = __shfl_sync(0xffffffffu, att_oct, (row & 7) * 4);
            int ridx = __shfl_sync(0xffffffffu, idx, row);
            float4 v = *(const float4*)(u2e + (size_t)ridx * D + ecol);
            a0 = fmaf(attr, v.x, a0);
            a1 = fmaf(attr, v.y, a1);
            a2 = fmaf(attr, v.z, a2);
            a3 = fmaf(attr, v.w, a3);
        }
        a0 += __shfl_xor_sync(0xffffffffu, a0, 16);
        a1 += __shfl_xor_sync(0xffffffffu, a1, 16);
        a2 += __shfl_xor_sync(0xffffffffu, a2, 16);
        a3 += __shfl_xor_sync(0xffffffffu, a3, 16);
        if (lane < 16)
            *(float4*)(out + (size_t)n * D + ecol) = make_float4(a0, a1, a2, a3);

        // ---- tail: build NEXT node's A tile in the alternate buffer ----
        {
            unsigned char* tN = smem + (warp * 2 + (cur ^ 1)) * TILE_B;
#pragma unroll
            for (int it = 0; it < 8; it++) {
                uint4 w;
                ADD_BF16X2(w.x, p42[it].x, q42.x); MAX_BF16X2(w.x, w.x, 0u);
                ADD_BF16X2(w.y, p42[it].y, q42.y); MAX_BF16X2(w.y, w.y, 0u);
                ADD_BF16X2(w.z, p42[it].z, q42.z); MAX_BF16X2(w.z, w.z, 0u);
                ADD_BF16X2(w.w, p42[it].w, q42.w); MAX_BF16X2(w.w, w.w, 0u);
                *(uint4*)(tN + (it * 4 + rsub) * ASTRIDE_B + seg * 16) = w;
            }
        }
        __syncwarp();
        idx = idx2; m = m2; cur ^= 1;
    }
}

// ======================= launch =======================
// Input order (metadata): u2e, W1, b1, W2, b2, W3, b3, nodes, neigh_idx, neigh_mask
extern "C" void kernel_launch(void* const* d_in, const int* in_sizes, int n_in,
                              void* d_out, int out_size) {
    const float* u2e = (const float*)d_in[0];
    const float* W1  = (const float*)d_in[1];
    const float* b1  = (const float*)d_in[2];
    const float* W2  = (const float*)d_in[3];
    const float* b2  = (const float*)d_in[4];
    const float* W3  = (const float*)d_in[5];
    const int*   nodes     = (const int*)d_in[7];
    const int*   neigh_idx = (const int*)d_in[8];
    const void*  neigh_mask = d_in[9];
    float* out = (float*)d_out;

    int V = in_sizes[0] / D;
    if (V > VOCAB_MAX) V = VOCAB_MAX;
    int n_nodes = in_sizes[7];
    int n_words = in_sizes[9] / 4;   // safe lower bound under both dtypes

    prep_mma_kernel<<<(V + 127) / 128, 128>>>(u2e, W1, b1, V,
                                              (const unsigned int*)neigh_mask, n_words);
    static int smem_set = 0;
    if (!smem_set) {
        cudaFuncSetAttribute(agg_mma_kernel,
                             cudaFuncAttributeMaxDynamicSharedMemorySize, AGG_SMEM_TOT);
        smem_set = 1;
    }
    agg_mma_kernel<<<296, 256, AGG_SMEM_TOT>>>(u2e, W2, b2, W3,
                                               nodes, neigh_idx, neigh_mask, out, n_nodes);
}